// round 10
// baseline (speedup 1.0000x reference)
#include <cuda_runtime.h>
#include <cuda_bf16.h>
#include <stdint.h>
#include <math.h>

// R10: pair-of-N-tiles per pipeline iteration (24 MMAs per sync), 2-stage B ring.

// ---------------- problem constants (fixed shapes) ----------------
#define NSRC0   60000
#define NDST0   30000
#define E0      480000
#define NSRC1   30000
#define NDST1   8000
#define E1      128000
#define IMG_D   1024
#define BLK_D   768
#define FUSED   512
#define HEADS   8
#define HID     64
#define OUT_D   128

// ---------------- scratch (static __device__, no allocs) ----------------
__device__ __align__(16) float g_fi[(size_t)NSRC0 * FUSED];
__device__ __align__(16) float g_ti[(size_t)NSRC0 * FUSED];
__device__ __align__(16) float g_gv[(size_t)NSRC0 * FUSED];
__device__ __align__(16) float g_fused[(size_t)NSRC0 * FUSED];
__device__ __align__(16) float g_z1[(size_t)NSRC0 * FUSED];
__device__ __align__(16) float g_s1s[(size_t)NSRC0 * HEADS];
__device__ __align__(16) float g_s1d[(size_t)NSRC0 * HEADS];
__device__ __align__(16) float g_h[(size_t)NDST0 * FUSED];
__device__ __align__(16) float g_z2[(size_t)NSRC1 * OUT_D];
__device__ __align__(16) float g_s2s[NSRC1];
__device__ __align__(16) float g_s2d[NSRC1];

__device__ __align__(16) __nv_bfloat16 g_WimgH[FUSED * IMG_D];
__device__ __align__(16) __nv_bfloat16 g_WimgL[FUSED * IMG_D];
__device__ __align__(16) __nv_bfloat16 g_WblkH[FUSED * BLK_D];
__device__ __align__(16) __nv_bfloat16 g_WblkL[FUSED * BLK_D];
__device__ __align__(16) __nv_bfloat16 g_WvTH[FUSED * FUSED];
__device__ __align__(16) __nv_bfloat16 g_WvTL[FUSED * FUSED];
__device__ __align__(16) __nv_bfloat16 g_WeTH[FUSED * FUSED];
__device__ __align__(16) __nv_bfloat16 g_WeTL[FUSED * FUSED];
__device__ __align__(16) __nv_bfloat16 g_fc1H[FUSED * FUSED];
__device__ __align__(16) __nv_bfloat16 g_fc1L[FUSED * FUSED];
__device__ __align__(16) __nv_bfloat16 g_fc2H[OUT_D * FUSED];
__device__ __align__(16) __nv_bfloat16 g_fc2L[OUT_D * FUSED];

__device__ int g_cnt0[NDST0];
__device__ int g_off0[NDST0 + 1];
__device__ int g_cur0[NDST0];
__device__ int g_csr0[E0];    // SRC node id per CSR slot
__device__ int g_cnt1[NDST1];
__device__ int g_off1[NDST1 + 1];
__device__ int g_cur1[NDST1];
__device__ int g_csr1[E1];

// ==================== common helpers ====================
__device__ __forceinline__ uint32_t smem_u32(const void* p) {
    uint32_t a;
    asm("{ .reg .u64 t; cvta.to.shared.u64 t, %1; cvt.u32.u64 %0, t; }" : "=r"(a) : "l"(p));
    return a;
}
__device__ __forceinline__ float sigm(float x) { return 1.f / (1.f + __expf(-x)); }

// ==================== tcgen05 macros ====================
#define TCGEN05_ALLOC(saddr, ncols) \
    asm volatile("tcgen05.alloc.cta_group::1.sync.aligned.shared::cta.b32 [%0], %1;" \
                 :: "r"((uint32_t)(saddr)), "r"((uint32_t)(ncols)) : "memory")
#define TCGEN05_RELINQ() \
    asm volatile("tcgen05.relinquish_alloc_permit.cta_group::1.sync.aligned;")
#define TCGEN05_DEALLOC(tm, ncols) \
    asm volatile("tcgen05.dealloc.cta_group::1.sync.aligned.b32 %0, %1;" :: "r"(tm), "r"((uint32_t)(ncols)))
#define TCGEN05_COMMIT(mbar) \
    asm volatile("tcgen05.commit.cta_group::1.mbarrier::arrive::one.shared::cluster.b64 [%0];" \
                 :: "r"((uint32_t)(mbar)) : "memory")
#define TCGEN05_FENCE_AFTER() asm volatile("tcgen05.fence::after_thread_sync;" ::: "memory")
#define TCGEN05_FENCE_BEFORE() asm volatile("tcgen05.fence::before_thread_sync;" ::: "memory")
#define TCGEN05_WAIT_LD() asm volatile("tcgen05.wait::ld.sync.aligned;" ::: "memory")
#define FENCE_ASYNC_SHARED() asm volatile("fence.proxy.async.shared::cta;" ::: "memory")
#define MBARRIER_INIT(mbar, cnt) \
    asm volatile("mbarrier.init.shared.b64 [%0], %1;" :: "r"((uint32_t)(mbar)), "r"((uint32_t)(cnt)) : "memory")

#define MBARRIER_WAIT_PARITY(mbar_addr, phase_parity) do { \
    uint32_t _mbar = (uint32_t)(mbar_addr); \
    uint32_t _par = (uint32_t)(phase_parity); \
    uint32_t _done; \
    asm volatile("{\n\t.reg .pred p;\n\t" \
        "mbarrier.try_wait.parity.acquire.cta.shared::cta.b64 p, [%1], %2;\n\t" \
        "selp.b32 %0, 1, 0, p;\n\t}" : "=r"(_done) : "r"(_mbar), "r"(_par) : "memory"); \
    if (!_done) { \
        asm volatile("{\n\t.reg .pred P1;\n\t" \
            "WL_%=:\n\t" \
            "mbarrier.try_wait.parity.acquire.cta.shared::cta.b64 P1, [%0], %1, 0x989680;\n\t" \
            "@P1 bra.uni WD_%=;\n\t" \
            "bra.uni WL_%=;\n\t" \
            "WD_%=:\n\t}" :: "r"(_mbar), "r"(_par) : "memory"); \
    } \
} while (0)

#define TCGEN05_LD_32X32B_X32(r, tmem_addr) \
    asm volatile( \
        "tcgen05.ld.sync.aligned.32x32b.x32.b32 " \
        "{%0, %1, %2, %3, %4, %5, %6, %7, " \
        " %8, %9, %10, %11, %12, %13, %14, %15, " \
        " %16, %17, %18, %19, %20, %21, %22, %23, " \
        " %24, %25, %26, %27, %28, %29, %30, %31}, [%32];" \
        : "=r"((r)[0]),  "=r"((r)[1]),  "=r"((r)[2]),  "=r"((r)[3]), \
          "=r"((r)[4]),  "=r"((r)[5]),  "=r"((r)[6]),  "=r"((r)[7]), \
          "=r"((r)[8]),  "=r"((r)[9]),  "=r"((r)[10]), "=r"((r)[11]), \
          "=r"((r)[12]), "=r"((r)[13]), "=r"((r)[14]), "=r"((r)[15]), \
          "=r"((r)[16]), "=r"((r)[17]), "=r"((r)[18]), "=r"((r)[19]), \
          "=r"((r)[20]), "=r"((r)[21]), "=r"((r)[22]), "=r"((r)[23]), \
          "=r"((r)[24]), "=r"((r)[25]), "=r"((r)[26]), "=r"((r)[27]), \
          "=r"((r)[28]), "=r"((r)[29]), "=r"((r)[30]), "=r"((r)[31]) \
        : "r"(tmem_addr))

static __device__ __forceinline__ uint64_t make_desc(uint32_t saddr) {
    const uint64_t base = (uint64_t(2) << 61) | (uint64_t(1) << 46) |
                          (uint64_t(64) << 32) | (uint64_t(1) << 16);
    return base | ((uint64_t)(saddr >> 4) & 0x3FFF);
}
#define GT_IDESC 0x8200490u

__device__ __forceinline__ void mma_f16_ss(uint32_t d, uint64_t a, uint64_t b,
                                           uint32_t idesc, uint32_t en) {
#if defined(__CUDA_ARCH__) && defined(__CUDA_ARCH_FEAT_SM103_ALL)
    asm volatile(
        "{\n\t.reg .pred p;\n\tsetp.ne.u32 p, %4, 0;\n\t"
        "tcgen05.mma.cta_group::1.kind::f16 [%0], %1, %2, %3, {%5,%5,%5,%5}, p;\n\t}"
        :: "r"(d), "l"(a), "l"(b), "r"(idesc), "r"(en), "r"(0u)
        : "memory");
#else
    (void)d; (void)a; (void)b; (void)idesc; (void)en;
#endif
}

// ==================== cp.async ====================
#define CP_ASYNC16(dst, src) \
    asm volatile("cp.async.cg.shared.global [%0], [%1], 16;" :: "r"(dst), "l"(src) : "memory")
#define CP_ASYNC_COMMIT() \
    asm volatile("cp.async.commit_group;" ::: "memory")
#define CP_ASYNC_WAIT0() \
    asm volatile("cp.async.wait_group 0;" ::: "memory")
#define CP_ASYNC_WAIT1() \
    asm volatile("cp.async.wait_group 1;" ::: "memory")

// ==================== mma.sync fallback macros ====================
#define LDSM_X4(r0, r1, r2, r3, addr) \
    asm volatile("ldmatrix.sync.aligned.m8n8.x4.shared.b16 {%0,%1,%2,%3}, [%4];" \
                 : "=r"(r0), "=r"(r1), "=r"(r2), "=r"(r3) : "r"(addr))
#define MMA_BF16(c, a, b) \
    asm volatile("mma.sync.aligned.m16n8k16.row.col.f32.bf16.bf16.f32 " \
                 "{%0,%1,%2,%3},{%4,%5,%6,%7},{%8,%9},{%0,%1,%2,%3};" \
                 : "+f"((c)[0]), "+f"((c)[1]), "+f"((c)[2]), "+f"((c)[3]) \
                 : "r"((a)[0]), "r"((a)[1]), "r"((a)[2]), "r"((a)[3]), \
                   "r"((b)[0]), "r"((b)[1]))

// ==================== GEMM (NT) with fused epilogues ====================
// MODE 0: C = A*B^T
// MODE 1: GEMM -> ge; epilogue: C(=fused) = sig(ge+be)*ti + sig(gv+bv)*fi   (NT=4)
// MODE 2: C = z1; s0out/s1out = per-(row,head) dots with P0=a1 [8][128]     (NT=4)
// MODE 3: C = z2; s0out/s1out = per-row dots with P0=a2 [256]               (NT=1)
#define GT_THREADS 512
#define SM_A_OFF 1024
#define SM_B_OFF (1024 + 65536)
#define SM_TOTAL (1024 + 65536 + 131072)
// barriers: A slots @16,24   B slots @32,40   done @56
// B stage (65536 B): Bh(n0)@0 Bl(n0)@16384 Bh(n1)@32768 Bl(n1)@49152

// B tile (128 rows x 64 bf16) -> SW128 smem via cp.async
__device__ __forceinline__ void load_tile_bf16_async(const __nv_bfloat16* __restrict__ src,
                                                     int ldk, int row0, int k0,
                                                     uint32_t dstu, int tid) {
#pragma unroll
    for (int c = 0; c < 2; c++) {
        int chunk = tid + c * GT_THREADS;
        int r = chunk >> 3, c16 = chunk & 7;
        uint32_t off = (uint32_t)(r * 128 + c16 * 16);
        uint32_t sw = off ^ ((off >> 3) & 0x70);
        CP_ASYNC16(dstu + sw, src + (size_t)(row0 + r) * ldk + k0 + c16 * 8);
    }
}

// B tile synchronous (fallback path)
__device__ __forceinline__ void load_tile_bf16(const __nv_bfloat16* __restrict__ src,
                                               int ldk, int row0, int k0,
                                               char* dst, int tid) {
#pragma unroll
    for (int c = 0; c < 2; c++) {
        int chunk = tid + c * GT_THREADS;
        int r = chunk >> 3, c16 = chunk & 7;
        uint32_t off = (uint32_t)(r * 128 + c16 * 16);
        uint32_t sw = off ^ ((off >> 3) & 0x70);
        float4 v = *(const float4*)(src + (size_t)(row0 + r) * ldk + k0 + c16 * 8);
        *(float4*)(dst + sw) = v;
    }
}

// A 128x64 fp32 -> hi/lo bf16 SW128 tiles; zero rows >= rowMax
__device__ __forceinline__ void load_tile_cvt(const float* __restrict__ src,
                                              int ldk, int row0, int rowMax, int k0,
                                              char* hidst, char* lodst, int tid) {
#pragma unroll
    for (int c = 0; c < 2; c++) {
        int chunk = tid + c * GT_THREADS;
        int r = chunk >> 3, c16 = chunk & 7;
        uint32_t off = (uint32_t)(r * 128 + c16 * 16);
        uint32_t sw = off ^ ((off >> 3) & 0x70);
        int gr = row0 + r;
        float4 v0 = make_float4(0.f, 0.f, 0.f, 0.f);
        float4 v1 = make_float4(0.f, 0.f, 0.f, 0.f);
        if (gr < rowMax) {
            const float* p = src + (size_t)gr * ldk + k0 + c16 * 8;
            v0 = *(const float4*)p;
            v1 = *(const float4*)(p + 4);
        }
        float f[8] = {v0.x, v0.y, v0.z, v0.w, v1.x, v1.y, v1.z, v1.w};
        __nv_bfloat162 h[4], l[4];
#pragma unroll
        for (int j = 0; j < 4; j++) {
            __nv_bfloat16 h0 = __float2bfloat16(f[2 * j]);
            __nv_bfloat16 h1 = __float2bfloat16(f[2 * j + 1]);
            h[j].x = h0; h[j].y = h1;
            l[j].x = __float2bfloat16(f[2 * j] - __bfloat162float(h0));
            l[j].y = __float2bfloat16(f[2 * j + 1] - __bfloat162float(h1));
        }
        *(float4*)(hidst + sw) = *(float4*)h;
        *(float4*)(lodst + sw) = *(float4*)l;
    }
}

template <int MODE>
__global__ void __launch_bounds__(GT_THREADS, 1)
gemm_tc_x(const float* __restrict__ A,
          const __nv_bfloat16* __restrict__ Bh, const __nv_bfloat16* __restrict__ Bl,
          float* __restrict__ C, int M, int N, int K,
          const float* __restrict__ P0, const float* __restrict__ P1,
          const float* __restrict__ P2, const float* __restrict__ P3,
          const float* __restrict__ P4,
          float* __restrict__ s0out, float* __restrict__ s1out) {
    extern __shared__ __align__(1024) char smem[];
    const int tid = threadIdx.x;
    const int wid = tid >> 5, lane = tid & 31;
    const int row0 = blockIdx.x * 128;
    const int NT = N >> 7;
    const int KCN = K >> 6;

#if defined(__CUDA_ARCH__) && !defined(__CUDA_ARCH_FEAT_SM103_ALL)
    // ================= fallback: mma.sync bf16 (warps 0-7 compute, all load) =================
    const int wm = wid & 3;
    const int wn = (wid >> 2) & 1;
    char* sAh = smem + SM_A_OFF;
    char* sAl = smem + SM_A_OFF + 16384;
    char* sBh = smem + SM_B_OFF;
    char* sBl = smem + SM_B_OFF + 16384;
    const uint32_t uAh = smem_u32(sAh), uAl = smem_u32(sAl);
    const uint32_t uBh = smem_u32(sBh), uBl = smem_u32(sBl);
    const int g = lane >> 3, r8 = lane & 7;
    float* redf = (float*)(smem);

    for (int n = 0; n < NT; n++) {
        float acc[2][8][4];
#pragma unroll
        for (int mt = 0; mt < 2; mt++)
#pragma unroll
            for (int nt = 0; nt < 8; nt++)
#pragma unroll
                for (int e = 0; e < 4; e++) acc[mt][nt][e] = 0.f;

        for (int k = 0; k < KCN; k++) {
            __syncthreads();
            load_tile_cvt(A, K, row0, M, k * 64, sAh, sAl, tid);
            load_tile_bf16(Bh, K, n * 128, k * 64, sBh, tid);
            load_tile_bf16(Bl, K, n * 128, k * 64, sBl, tid);
            __syncthreads();
            if (wid < 8) {
#pragma unroll
                for (int kk = 0; kk < 4; kk++) {
                    const int kb = kk * 32 + (g >> 1) * 16;
                    uint32_t ah[2][4], al[2][4], bh[8][2], bl[8][2];
#pragma unroll
                    for (int mt = 0; mt < 2; mt++) {
                        uint32_t off = (uint32_t)((wm * 32 + mt * 16 + (g & 1) * 8 + r8) * 128 + kb);
                        uint32_t sw = off ^ ((off >> 3) & 0x70);
                        LDSM_X4(ah[mt][0], ah[mt][1], ah[mt][2], ah[mt][3], uAh + sw);
                        LDSM_X4(al[mt][0], al[mt][1], al[mt][2], al[mt][3], uAl + sw);
                    }
#pragma unroll
                    for (int bt = 0; bt < 4; bt++) {
                        uint32_t off = (uint32_t)((wn * 64 + bt * 16 + (g & 1) * 8 + r8) * 128 + kb);
                        uint32_t sw = off ^ ((off >> 3) & 0x70);
                        uint32_t r0, r1, r2, r3;
                        LDSM_X4(r0, r1, r2, r3, uBh + sw);
                        bh[bt * 2][0] = r0; bh[bt * 2][1] = r2;
                        bh[bt * 2 + 1][0] = r1; bh[bt * 2 + 1][1] = r3;
                        LDSM_X4(r0, r1, r2, r3, uBl + sw);
                        bl[bt * 2][0] = r0; bl[bt * 2][1] = r2;
                        bl[bt * 2 + 1][0] = r1; bl[bt * 2 + 1][1] = r3;
                    }
#pragma unroll
                    for (int mt = 0; mt < 2; mt++)
#pragma unroll
                        for (int nt = 0; nt < 8; nt++) {
                            MMA_BF16(acc[mt][nt], ah[mt], bh[nt]);
                            MMA_BF16(acc[mt][nt], ah[mt], bl[nt]);
                            MMA_BF16(acc[mt][nt], al[mt], bh[nt]);
                        }
                }
            }
        }
        __syncthreads();
        if (wid < 8) {
            const int hn = n * 2 + wn;
#pragma unroll
            for (int mt = 0; mt < 2; mt++) {
                int rr = row0 + wm * 32 + mt * 16 + (lane >> 2);
                float p0a = 0.f, p1a = 0.f, p0b = 0.f, p1b = 0.f;
#pragma unroll
                for (int nt = 0; nt < 8; nt++) {
                    int col = n * 128 + wn * 64 + nt * 8 + (lane & 3) * 2;
                    float v0 = acc[mt][nt][0], v1 = acc[mt][nt][1];
                    float v2 = acc[mt][nt][2], v3 = acc[mt][nt][3];
                    if (MODE == 2) {
                        int c = nt * 8 + (lane & 3) * 2;
                        float aS0 = __ldg(&P0[hn * 128 + c]),      aS1 = __ldg(&P0[hn * 128 + c + 1]);
                        float aD0 = __ldg(&P0[hn * 128 + 64 + c]), aD1 = __ldg(&P0[hn * 128 + 64 + c + 1]);
                        p0a += v0 * aS0 + v1 * aS1;  p1a += v0 * aD0 + v1 * aD1;
                        p0b += v2 * aS0 + v3 * aS1;  p1b += v2 * aD0 + v3 * aD1;
                    }
                    if (MODE == 3) {
                        float aS0 = __ldg(&P0[col]),       aS1 = __ldg(&P0[col + 1]);
                        float aD0 = __ldg(&P0[128 + col]), aD1 = __ldg(&P0[128 + col + 1]);
                        p0a += v0 * aS0 + v1 * aS1;  p1a += v0 * aD0 + v1 * aD1;
                        p0b += v2 * aS0 + v3 * aS1;  p1b += v2 * aD0 + v3 * aD1;
                    }
                    if (MODE == 1) {
                        float bv0 = __ldg(&P3[col]), bv1 = __ldg(&P3[col + 1]);
                        float be0 = __ldg(&P4[col]), be1 = __ldg(&P4[col + 1]);
                        if (rr < M) {
                            size_t o = (size_t)rr * N + col;
                            v0 = sigm(v0 + be0) * __ldg(&P2[o]) + sigm(__ldg(&P0[o]) + bv0) * __ldg(&P1[o]);
                            v1 = sigm(v1 + be1) * __ldg(&P2[o+1]) + sigm(__ldg(&P0[o+1]) + bv1) * __ldg(&P1[o+1]);
                        }
                        if (rr + 8 < M) {
                            size_t o = (size_t)(rr + 8) * N + col;
                            v2 = sigm(v2 + be0) * __ldg(&P2[o]) + sigm(__ldg(&P0[o]) + bv0) * __ldg(&P1[o]);
                            v3 = sigm(v3 + be1) * __ldg(&P2[o+1]) + sigm(__ldg(&P0[o+1]) + bv1) * __ldg(&P1[o+1]);
                        }
                    }
                    if (rr < M)     *(float2*)&C[(size_t)rr * N + col] = make_float2(v0, v1);
                    if (rr + 8 < M) *(float2*)&C[(size_t)(rr + 8) * N + col] = make_float2(v2, v3);
                }
                if (MODE == 2 || MODE == 3) {
                    p0a += __shfl_xor_sync(0xffffffffu, p0a, 1); p0a += __shfl_xor_sync(0xffffffffu, p0a, 2);
                    p1a += __shfl_xor_sync(0xffffffffu, p1a, 1); p1a += __shfl_xor_sync(0xffffffffu, p1a, 2);
                    p0b += __shfl_xor_sync(0xffffffffu, p0b, 1); p0b += __shfl_xor_sync(0xffffffffu, p0b, 2);
                    p1b += __shfl_xor_sync(0xffffffffu, p1b, 1); p1b += __shfl_xor_sync(0xffffffffu, p1b, 2);
                    if ((lane & 3) == 0) {
                        if (MODE == 2) {
                            if (rr < M)     { s0out[(size_t)rr * 8 + hn] = p0a; s1out[(size_t)rr * 8 + hn] = p1a; }
                            if (rr + 8 < M) { s0out[(size_t)(rr + 8) * 8 + hn] = p0b; s1out[(size_t)(rr + 8) * 8 + hn] = p1b; }
                        } else {
                            int lr = wm * 32 + mt * 16 + (lane >> 2);
                            redf[(wn * 128 + lr) * 2 + 0] = p0a;
                            redf[(wn * 128 + lr) * 2 + 1] = p1a;
                            redf[(wn * 128 + lr + 8) * 2 + 0] = p0b;
                            redf[(wn * 128 + lr + 8) * 2 + 1] = p1b;
                        }
                    }
                }
            }
        }
    }
    if (MODE == 3) {
        __syncthreads();
        if (tid < 128 && row0 + tid < M) {
            s0out[row0 + tid] = redf[tid * 2] + redf[(128 + tid) * 2];
            s1out[row0 + tid] = redf[tid * 2 + 1] + redf[(128 + tid) * 2 + 1];
        }
    }
#else
    // ================= tcgen05 path: n-pair iterations, 2-stage B ring =================
    uint32_t sbase = smem_u32(smem);
    if (wid == 0) { TCGEN05_ALLOC(sbase, 512); TCGEN05_RELINQ(); }
    if (tid == 0) {
        MBARRIER_INIT(sbase + 16, 1);
        MBARRIER_INIT(sbase + 24, 1);
        MBARRIER_INIT(sbase + 32, 1);
        MBARRIER_INIT(sbase + 40, 1);
        MBARRIER_INIT(sbase + 56, 1);
    }
    __syncthreads();
    uint32_t tmem;
    asm volatile("ld.shared.b32 %0, [%1];" : "=r"(tmem) : "r"(sbase));

    const int NTH = (NT + 1) >> 1;       // n-pairs per k chunk
    const int ITER = KCN * NTH;
    uint32_t pa = 0, pb = 0;

    // stage loader: B pair (n0, n0+1 if valid) for chunk k into stage slot
    // (lambda-free to keep ptxas happy: inline twice via macro)
#define LOAD_B_PAIR(kk_, n0_, slot_) do { \
        uint32_t st = sbase + SM_B_OFF + (slot_) * 65536;                              \
        load_tile_bf16_async(Bh, K, (n0_) * 128, (kk_) * 64, st, tid);                 \
        load_tile_bf16_async(Bl, K, (n0_) * 128, (kk_) * 64, st + 16384, tid);         \
        if ((n0_) + 1 < NT) {                                                          \
            load_tile_bf16_async(Bh, K, ((n0_) + 1) * 128, (kk_) * 64, st + 32768, tid); \
            load_tile_bf16_async(Bl, K, ((n0_) + 1) * 128, (kk_) * 64, st + 49152, tid); \
        }                                                                              \
        CP_ASYNC_COMMIT();                                                             \
    } while (0)

    // prologue: stages for iter 0,1 in flight; A chunk 0 resident
    LOAD_B_PAIR(0, 0, 0);
    if (ITER > 1) {
        int k1 = 1 / NTH, p1 = 1 % NTH;
        LOAD_B_PAIR(k1, 2 * p1, 1);
    }
    load_tile_cvt(A, K, row0, M, 0, smem + SM_A_OFF, smem + SM_A_OFF + 16384, tid);

    for (int iter = 0; iter < ITER; iter++) {
        const int k = iter / NTH, p = iter - k * NTH;
        const int n0 = 2 * p;
        const int sa = k & 1;
        const int sb = iter & 1;

        if (iter + 1 < ITER) CP_ASYNC_WAIT1(); else CP_ASYNC_WAIT0();
        FENCE_ASYNC_SHARED();
        __syncthreads();

        if (tid == 0) {
            uint64_t adh = make_desc(sbase + SM_A_OFF + sa * 32768);
            uint64_t adl = make_desc(sbase + SM_A_OFF + sa * 32768 + 16384);
            uint32_t stb = sbase + SM_B_OFF + sb * 65536;
#pragma unroll
            for (int nn = 0; nn < 2; nn++) {
                if (n0 + nn >= NT) break;
                uint64_t bdh = make_desc(stb + nn * 32768);
                uint64_t bdl = make_desc(stb + nn * 32768 + 16384);
                uint32_t d = tmem + (n0 + nn) * 128;
#pragma unroll
                for (int t = 0; t < 4; t++)
                    mma_f16_ss(d, adh + t * 2, bdh + t * 2, GT_IDESC,
                               (k > 0 || t > 0) ? 1u : 0u);
#pragma unroll
                for (int t = 0; t < 4; t++)
                    mma_f16_ss(d, adh + t * 2, bdl + t * 2, GT_IDESC, 1u);
#pragma unroll
                for (int t = 0; t < 4; t++)
                    mma_f16_ss(d, adl + t * 2, bdh + t * 2, GT_IDESC, 1u);
            }
            TCGEN05_COMMIT(sbase + 32 + sb * 8);
            if (p == NTH - 1) TCGEN05_COMMIT(sbase + 16 + sa * 8);
            if (iter == ITER - 1) TCGEN05_COMMIT(sbase + 56);
        }

        // prefetch B pair for iter+2 (same slot: wait this iter's MMA commit)
        if (iter + 2 < ITER) {
            MBARRIER_WAIT_PARITY(sbase + 32 + sb * 8, (pb >> sb) & 1u);
            pb ^= (1u << sb);
            const int i2 = iter + 2;
            const int k2 = i2 / NTH, p2 = i2 - k2 * NTH;
            LOAD_B_PAIR(k2, 2 * p2, sb);
        }

        // prefetch A chunk k+1 during first pair of chunk k
        if (p == 0 && k + 1 < KCN) {
            const int sa2 = (k + 1) & 1;
            if (k >= 1) {
                MBARRIER_WAIT_PARITY(sbase + 16 + sa2 * 8, (pa >> sa2) & 1u);
                pa ^= (1u << sa2);
            }
            load_tile_cvt(A, K, row0, M, (k + 1) * 64,
                          smem + SM_A_OFF + sa2 * 32768,
                          smem + SM_A_OFF + sa2 * 32768 + 16384, tid);
        }
    }
#undef LOAD_B_PAIR

    __syncthreads();
    MBARRIER_WAIT_PARITY(sbase + 56, 0);
    TCGEN05_FENCE_AFTER();

    // epilogue: 16 warps, 4 groups over column blocks (stride 4)
    const int eg = wid >> 2;
    const int lrow = (wid & 3) * 32 + lane;
    const int row = row0 + lrow;
    float* red = (float*)(smem + SM_A_OFF);  // tiles dead

    for (int cb = eg; cb < NT * 4; cb += 4) {
        uint32_t r[32];
        TCGEN05_LD_32X32B_X32(r, tmem + cb * 32);
        TCGEN05_WAIT_LD();
        float v[32];
#pragma unroll
        for (int c = 0; c < 32; c++) v[c] = __uint_as_float(r[c]);

        if (MODE == 1) {
            if (row < M) {
                const float4* gv4 = (const float4*)(P0 + (size_t)row * N + cb * 32);
                const float4* fi4 = (const float4*)(P1 + (size_t)row * N + cb * 32);
                const float4* ti4 = (const float4*)(P2 + (size_t)row * N + cb * 32);
                const float4* bv4 = (const float4*)(P3 + cb * 32);
                const float4* be4 = (const float4*)(P4 + cb * 32);
                float4* cp = (float4*)(C + (size_t)row * N + cb * 32);
#pragma unroll
                for (int j = 0; j < 8; j++) {
                    float4 gg = __ldg(&gv4[j]), ff = __ldg(&fi4[j]), tt = __ldg(&ti4[j]);
                    float4 bb = __ldg(&bv4[j]), ee = __ldg(&be4[j]);
                    float4 o;
                    o.x = sigm(v[4*j+0] + ee.x) * tt.x + sigm(gg.x + bb.x) * ff.x;
                    o.y = sigm(v[4*j+1] + ee.y) * tt.y + sigm(gg.y + bb.y) * ff.y;
                    o.z = sigm(v[4*j+2] + ee.z) * tt.z + sigm(gg.z + bb.z) * ff.z;
                    o.w = sigm(v[4*j+3] + ee.w) * tt.w + sigm(gg.w + bb.w) * ff.w;
                    cp[j] = o;
                }
            }
        } else {
            if (row < M) {
                float* cp = C + (size_t)row * N + cb * 32;
#pragma unroll
                for (int c = 0; c < 32; c += 4)
                    *(float4*)(cp + c) = make_float4(v[c], v[c+1], v[c+2], v[c+3]);
            }
            if (MODE == 2) {
                int head = cb >> 1;
                int within = (cb & 1) * 32;
                float s0 = 0.f, s1 = 0.f;
#pragma unroll
                for (int c = 0; c < 32; c++) {
                    s0 += v[c] * __ldg(&P0[head * 128 + within + c]);
                    s1 += v[c] * __ldg(&P0[head * 128 + 64 + within + c]);
                }
                red[(cb * 128 + lrow) * 2 + 0] = s0;
                red[(cb * 128 + lrow) * 2 + 1] = s1;
            }
            if (MODE == 3) {
                float s0 = 0.f, s1 = 0.f;
#pragma unroll
                for (int c = 0; c < 32; c++) {
                    int col = cb * 32 + c;
                    s0 += v[c] * __ldg(&P0[col]);
                    s1 += v[c] * __ldg(&P0[128 + col]);
                }
                red[(cb * 128 + lrow) * 2 + 0] = s0;
                red[(cb * 128 + lrow) * 2 + 1] = s1;
            }
        }
    }
    TCGEN05_FENCE_BEFORE();
    __syncthreads();
    if (MODE == 2) {
        for (int idx = tid; idx < 1024; idx += GT_THREADS) {
            int lr = idx >> 3, h = idx & 7;
            if (row0 + lr < M) {
                s0out[(size_t)(row0 + lr) * 8 + h] =
                    red[((2*h) * 128 + lr) * 2] + red[((2*h+1) * 128 + lr) * 2];
                s1out[(size_t)(row0 + lr) * 8 + h] =
                    red[((2*h) * 128 + lr) * 2 + 1] + red[((2*h+1) * 128 + lr) * 2 + 1];
            }
        }
    }
    if (MODE == 3) {
        if (tid < 128 && row0 + tid < M) {
            float s0 = 0.f, s1 = 0.f;
#pragma unroll
            for (int cb = 0; cb < 4; cb++) {
                s0 += red[(cb * 128 + tid) * 2];
                s1 += red[(cb * 128 + tid) * 2 + 1];
            }
            s0out[row0 + tid] = s0;
            s1out[row0 + tid] = s1;
        }
    }
    __syncthreads();
    if (wid == 0) TCGEN05_DEALLOC(tmem, 512);
#endif
}

// ---------------- weight prep ----------------
__global__ void cvt_hilo(const float* __restrict__ in, __nv_bfloat16* __restrict__ hi,
                         __nv_bfloat16* __restrict__ lo, int n4) {
    int i = blockIdx.x * blockDim.x + threadIdx.x;
    if (i >= n4) return;
    float4 v = ((const float4*)in)[i];
    float f[4] = {v.x, v.y, v.z, v.w};
    __nv_bfloat162 h01, h23, l01, l23;
    __nv_bfloat16 h0 = __float2bfloat16(f[0]), h1 = __float2bfloat16(f[1]);
    __nv_bfloat16 h2 = __float2bfloat16(f[2]), h3 = __float2bfloat16(f[3]);
    h01.x = h0; h01.y = h1; h23.x = h2; h23.y = h3;
    l01.x = __float2bfloat16(f[0] - __bfloat162float(h0));
    l01.y = __float2bfloat16(f[1] - __bfloat162float(h1));
    l23.x = __float2bfloat16(f[2] - __bfloat162float(h2));
    l23.y = __float2bfloat16(f[3] - __bfloat162float(h3));
    ((__nv_bfloat162*)hi)[2 * i] = h01;
    ((__nv_bfloat162*)hi)[2 * i + 1] = h23;
    ((__nv_bfloat162*)lo)[2 * i] = l01;
    ((__nv_bfloat162*)lo)[2 * i + 1] = l23;
}

__global__ void cvt_hilo_T(const float* __restrict__ in, __nv_bfloat16* __restrict__ hi,
                           __nv_bfloat16* __restrict__ lo) {
    __shared__ float t[32][33];
    int x = blockIdx.x * 32 + threadIdx.x;
    int y0 = blockIdx.y * 32 + threadIdx.y;
#pragma unroll
    for (int r = 0; r < 32; r += 8)
        t[threadIdx.y + r][threadIdx.x] = in[(size_t)(y0 + r) * 512 + x];
    __syncthreads();
    int x2 = blockIdx.y * 32 + threadIdx.x;
    int y2 = blockIdx.x * 32 + threadIdx.y;
#pragma unroll
    for (int r = 0; r < 32; r += 8) {
        float f = t[threadIdx.x][threadIdx.y + r];
        __nv_bfloat16 h = __float2bfloat16(f);
        hi[(size_t)(y2 + r) * 512 + x2] = h;
        lo[(size_t)(y2 + r) * 512 + x2] = __float2bfloat16(f - __bfloat162float(h));
    }
}

// ---------------- CSR build (csr stores SRC id) ----------------
__global__ void zero_int(int* p, int n) {
    int i = blockIdx.x * blockDim.x + threadIdx.x;
    if (i < n) p[i] = 0;
}
__global__ void edge_count(const int* __restrict__ dst, int* __restrict__ cnt, int E) {
    int i = blockIdx.x * blockDim.x + threadIdx.x;
    if (i < E) atomicAdd(&cnt[dst[i]], 1);
}
__global__ void scan_kernel(const int* __restrict__ cnt, int* __restrict__ off,
                            int* __restrict__ cursor, int n) {
    __shared__ int sh[1024];
    __shared__ int carry_s;
    int tid = threadIdx.x;
    if (tid == 0) carry_s = 0;
    __syncthreads();
    for (int base = 0; base < n; base += 1024) {
        int v = (base + tid < n) ? cnt[base + tid] : 0;
        sh[tid] = v;
        __syncthreads();
        for (int d = 1; d < 1024; d <<= 1) {
            int t = (tid >= d) ? sh[tid - d] : 0;
            __syncthreads();
            sh[tid] += t;
            __syncthreads();
        }
        int carry = carry_s;
        if (base + tid < n) {
            int ex = carry + sh[tid] - v;
            off[base + tid] = ex;
            cursor[base + tid] = ex;
        }
        __syncthreads();
        if (tid == 1023) carry_s = carry + sh[1023];
        __syncthreads();
    }
    if (tid == 0) off[n] = carry_s;
}
__global__ void edge_scatter(const int* __restrict__ src, const int* __restrict__ dst,
                             int* __restrict__ cursor, int* __restrict__ csr, int E) {
    int i = blockIdx.x * blockDim.x + threadIdx.x;
    if (i < E) {
        int p = atomicAdd(&cursor[dst[i]], 1);
        csr[p] = src[i];
    }
}

// ---------------- GAT layer 1: warp-per-dst softmax + aggregate + ELU ----------------
__global__ void gat_agg1(const int* __restrict__ off, const int* __restrict__ csr,
                         const float* __restrict__ ssrc, const float* __restrict__ sdst,
                         const float* __restrict__ z, float* __restrict__ hout, int nd) {
    int w = (blockIdx.x * blockDim.x + threadIdx.x) >> 5;
    int lane = threadIdx.x & 31;
    if (w >= nd) return;
    int h = lane & 7;
    int o0 = off[w], o1 = off[w + 1];
    float sd = sdst[(size_t)w * 8 + h];

    float mx = -1e30f;
    for (int i = o0; i < o1; i++) {
        int s = __ldg(&csr[i]);
        float v = __ldg(&ssrc[(size_t)s * 8 + h]) + sd;
        v = (v >= 0.f) ? v : 0.01f * v;
        mx = fmaxf(mx, v);
    }
    float den = 0.f;
    for (int i = o0; i < o1; i++) {
        int s = __ldg(&csr[i]);
        float v = __ldg(&ssrc[(size_t)s * 8 + h]) + sd;
        v = (v >= 0.f) ? v : 0.01f * v;
        den += __expf(v - mx);
    }
    float inv = 1.f / den;

    float acc[16];
#pragma unroll
    for (int j = 0; j < 16; j++) acc[j] = 0.f;

    for (int i = o0; i < o1; i++) {
        int s = __ldg(&csr[i]);
        float v = __ldg(&ssrc[(size_t)s * 8 + h]) + sd;
        v = (v >= 0.f) ? v : 0.01f * v;
        float al = __expf(v - mx) * inv;
        const float* zp = z + (size_t)s * FUSED;
#pragma unroll
        for (int j = 0; j < 16; j++) {
            float a = __shfl_sync(0xffffffffu, al, j >> 1);
            acc[j] += a * __ldg(&zp[j * 32 + lane]);
        }
    }
    float* hp = hout + (size_t)w * FUSED;
#pragma unroll
    for (int j = 0; j < 16; j++) {
        float x = acc[j];
        hp[j * 32 + lane] = (x > 0.f) ? x : (__expf(x) - 1.f);
    }
}

// ---------------- GAT layer 2 (1 head, O=128) -> d_out ----------------
__global__ void gat_agg2(const int* __restrict__ off, const int* __restrict__ csr,
                         const float* __restrict__ ssrc, const float* __restrict__ sdst,
                         const float* __restrict__ z, float* __restrict__ out, int nd) {
    int w = (blockIdx.x * blockDim.x + threadIdx.x) >> 5;
    int lane = threadIdx.x & 31;
    if (w >= nd) return;
    int o0 = off[w], o1 = off[w + 1];
    float sd = sdst[w];

    float mx = -1e30f;
    for (int i = o0; i < o1; i++) {
        int s = __ldg(&csr[i]);
        float v = __ldg(&ssrc[s]) + sd;
        v = (v >= 0.f) ? v : 0.01f * v;
        mx = fmaxf(mx, v);
    }
    float den = 0.f;
    for (int i = o0; i < o1; i++) {
        int s = __ldg(&csr[i]);
        float v = __ldg(&ssrc[s]) + sd;
        v = (v >= 0.f) ? v : 0.01f * v;
        den += __expf(v - mx);
    }
    float inv = 1.f / den;

    float a0 = 0.f, a1 = 0.f, a2 = 0.f, a3 = 0.f;
    for (int i = o0; i < o1; i++) {
        int s = __ldg(&csr[i]);
        float v = __ldg(&ssrc[s]) + sd;
        v = (v >= 0.f) ? v : 0.01f * v;
        float al = __expf(v - mx) * inv;
        const float* zp = z + (size_t)s * OUT_D;
        a0 += al * __ldg(&zp[lane]);
        a1 += al * __ldg(&zp[32 + lane]);
        a2 += al * __ldg(&zp[64 + lane]);
        a3 += al * __ldg(&zp[96 + lane]);
    }
    float* op = out + (size_t)w * OUT_D;
    op[lane] = a0;
    op[32 + lane] = a1;
    op[64 + lane] = a2;
    op[96 + lane] = a3;
}

// ---------------- host ----------------
extern "C" void kernel_launch(void* const* d_in, const int* in_sizes, int n_in,
                              void* d_out, int out_size) {
    const float* img   = (const float*)d_in[0];
    const float* blk   = (const float*)d_in[1];
    const float* W_img = (const float*)d_in[2];
    const float* W_blk = (const float*)d_in[3];
    const float* Wv    = (const float*)d_in[4];
    const float* bv    = (const float*)d_in[5];
    const float* We    = (const float*)d_in[6];
    const float* be    = (const float*)d_in[7];
    const float* fc1   = (const float*)d_in[8];
    const float* a1    = (const float*)d_in[9];
    const float* fc2   = (const float*)d_in[10];
    const float* a2    = (const float*)d_in[11];
    const int*   e0s   = (const int*)d_in[12];
    const int*   e0d   = (const int*)d_in[13];
    const int*   e1s   = (const int*)d_in[14];
    const int*   e1d   = (const int*)d_in[15];
    float* out = (float*)d_out;

    float *fi, *ti, *gv, *fused, *z1, *s1s, *s1d, *hbuf, *z2, *s2s, *s2d;
    __nv_bfloat16 *WimgH, *WimgL, *WblkH, *WblkL, *WvTH, *WvTL, *WeTH, *WeTL;
    __nv_bfloat16 *fc1H, *fc1L, *fc2H, *fc2L;
    int *cnt0, *off0, *cur0, *csr0, *cnt1, *off1, *cur1, *csr1;
    cudaGetSymbolAddress((void**)&fi, g_fi);
    cudaGetSymbolAddress((void**)&ti, g_ti);
    cudaGetSymbolAddress((void**)&gv, g_gv);
    cudaGetSymbolAddress((void**)&fused, g_fused);
    cudaGetSymbolAddress((void**)&z1, g_z1);
    cudaGetSymbolAddress((void**)&s1s, g_s1s);
    cudaGetSymbolAddress((void**)&s1d, g_s1d);
    cudaGetSymbolAddress((void**)&hbuf, g_h);
    cudaGetSymbolAddress((void**)&z2, g_z2);
    cudaGetSymbolAddress((void**)&s2s, g_s2s);
    cudaGetSymbolAddress((void**)&s2d, g_s2d);
    cudaGetSymbolAddress((void**)&WimgH, g_WimgH);
    cudaGetSymbolAddress((void**)&WimgL, g_WimgL);
    cudaGetSymbolAddress((void**)&WblkH, g_WblkH);
    cudaGetSymbolAddress((void**)&WblkL, g_WblkL);
    cudaGetSymbolAddress((void**)&WvTH, g_WvTH);
    cudaGetSymbolAddress((void**)&WvTL, g_WvTL);
    cudaGetSymbolAddress((void**)&WeTH, g_WeTH);
    cudaGetSymbolAddress((void**)&WeTL, g_WeTL);
    cudaGetSymbolAddress((void**)&fc1H, g_fc1H);
    cudaGetSymbolAddress((void**)&fc1L, g_fc1L);
    cudaGetSymbolAddress((void**)&fc2H, g_fc2H);
    cudaGetSymbolAddress((void**)&fc2L, g_fc2L);
    cudaGetSymbolAddress((void**)&cnt0, g_cnt0);
    cudaGetSymbolAddress((void**)&off0, g_off0);
    cudaGetSymbolAddress((void**)&cur0, g_cur0);
    cudaGetSymbolAddress((void**)&csr0, g_csr0);
    cudaGetSymbolAddress((void**)&cnt1, g_cnt1);
    cudaGetSymbolAddress((void**)&off1, g_off1);
    cudaGetSymbolAddress((void**)&cur1, g_cur1);
    cudaGetSymbolAddress((void**)&csr1, g_csr1);

    cudaFuncSetAttribute(gemm_tc_x<0>, cudaFuncAttributeMaxDynamicSharedMemorySize, SM_TOTAL);
    cudaFuncSetAttribute(gemm_tc_x<1>, cudaFuncAttributeMaxDynamicSharedMemorySize, SM_TOTAL);
    cudaFuncSetAttribute(gemm_tc_x<2>, cudaFuncAttributeMaxDynamicSharedMemorySize, SM_TOTAL);
    cudaFuncSetAttribute(gemm_tc_x<3>, cudaFuncAttributeMaxDynamicSharedMemorySize, SM_TOTAL);

    const dim3 tb(256);
    const dim3 tr_grid(16, 16), tr_blk(32, 8);
    const int MT0 = (NSRC0 + 127) / 128;
    const int MT1 = (NSRC1 + 127) / 128;
    const float* NP = nullptr;

    // prep needed by gemm1, then gemm1 as 4th launch (ncu window)
    cvt_hilo<<<(FUSED * IMG_D / 4 + 255) / 256, tb>>>(W_img, WimgH, WimgL, FUSED * IMG_D / 4);
    cvt_hilo<<<(FUSED * BLK_D / 4 + 255) / 256, tb>>>(W_blk, WblkH, WblkL, FUSED * BLK_D / 4);
    cvt_hilo_T<<<tr_grid, tr_blk>>>(Wv, WvTH, WvTL);
    gemm_tc_x<0><<<MT0, GT_THREADS, SM_TOTAL>>>(img, WimgH, WimgL, fi, NSRC0, FUSED, IMG_D,
                                                NP, NP, NP, NP, NP, nullptr, nullptr);
    cvt_hilo_T<<<tr_grid, tr_blk>>>(We, WeTH, WeTL);
    cvt_hilo<<<(FUSED * FUSED / 4 + 255) / 256, tb>>>(fc1, fc1H, fc1L, FUSED * FUSED / 4);
    cvt_hilo<<<(OUT_D * FUSED / 4 + 255) / 256, tb>>>(fc2, fc2H, fc2L, OUT_D * FUSED / 4);
    gemm_tc_x<0><<<MT0, GT_THREADS, SM_TOTAL>>>(blk, WblkH, WblkL, ti, NSRC0, FUSED, BLK_D,
                                                NP, NP, NP, NP, NP, nullptr, nullptr);

    // CSR builds
    zero_int<<<(NDST0 + 255) / 256, tb>>>(cnt0, NDST0);
    edge_count<<<(E0 + 255) / 256, tb>>>(e0d, cnt0, E0);
    scan_kernel<<<1, 1024>>>(cnt0, off0, cur0, NDST0);
    edge_scatter<<<(E0 + 255) / 256, tb>>>(e0s, e0d, cur0, csr0, E0);
    zero_int<<<(NDST1 + 255) / 256, tb>>>(cnt1, NDST1);
    edge_count<<<(E1 + 255) / 256, tb>>>(e1d, cnt1, E1);
    scan_kernel<<<1, 1024>>>(cnt1, off1, cur1, NDST1);
    edge_scatter<<<(E1 + 255) / 256, tb>>>(e1s, e1d, cur1, csr1, E1);

    // gv = fi x WvT ; fused = gate(ge) fused epilogue
    gemm_tc_x<0><<<MT0, GT_THREADS, SM_TOTAL>>>(fi, WvTH, WvTL, gv, NSRC0, FUSED, FUSED,
                                                NP, NP, NP, NP, NP, nullptr, nullptr);
    gemm_tc_x<1><<<MT0, GT_THREADS, SM_TOTAL>>>(ti, WeTH, WeTL, fused, NSRC0, FUSED, FUSED,
                                                gv, fi, ti, bv, be, nullptr, nullptr);

    // GAT layer 1
    gemm_tc_x<2><<<MT0, GT_THREADS, SM_TOTAL>>>(fused, fc1H, fc1L, z1, NSRC0, FUSED, FUSED,
                                                a1, NP, NP, NP, NP, s1s, s1d);
    gat_agg1<<<(NDST0 * 32 + 255) / 256, tb>>>(off0, csr0, s1s, s1d, z1, hbuf, NDST0);

    // GAT layer 2
    gemm_tc_x<3><<<MT1, GT_THREADS, SM_TOTAL>>>(hbuf, fc2H, fc2L, z2, NSRC1, OUT_D, FUSED,
                                                a2, NP, NP, NP, NP, s2s, s2d);
    gat_agg2<<<(NDST1 * 32 + 255) / 256, tb>>>(off1, csr1, s2s, s2d, z2, out, NDST1);

    (void)in_sizes; (void)n_in; (void)out_size;
}

// round 12
// speedup vs baseline: 1.0240x; 1.0240x over previous
#include <cuda_runtime.h>
#include <cuda_bf16.h>
#include <stdint.h>
#include <math.h>

// R11: B via single cp.async.bulk from pre-packed swizzled weights (kills LDGSTS issue bound).

// ---------------- problem constants (fixed shapes) ----------------
#define NSRC0   60000
#define NDST0   30000
#define E0      480000
#define NSRC1   30000
#define NDST1   8000
#define E1      128000
#define IMG_D   1024
#define BLK_D   768
#define FUSED   512
#define HEADS   8
#define HID     64
#define OUT_D   128

// ---------------- scratch (static __device__, no allocs) ----------------
__device__ __align__(16) float g_fi[(size_t)NSRC0 * FUSED];
__device__ __align__(16) float g_ti[(size_t)NSRC0 * FUSED];
__device__ __align__(16) float g_gv[(size_t)NSRC0 * FUSED];
__device__ __align__(16) float g_fused[(size_t)NSRC0 * FUSED];
__device__ __align__(16) float g_z1[(size_t)NSRC0 * FUSED];
__device__ __align__(16) float g_s1s[(size_t)NSRC0 * HEADS];
__device__ __align__(16) float g_s1d[(size_t)NSRC0 * HEADS];
__device__ __align__(16) float g_h[(size_t)NDST0 * FUSED];
__device__ __align__(16) float g_z2[(size_t)NSRC1 * OUT_D];
__device__ __align__(16) float g_s2s[NSRC1];
__device__ __align__(16) float g_s2d[NSRC1];

// flat hi/lo (fallback path)
__device__ __align__(16) __nv_bfloat16 g_WimgH[FUSED * IMG_D];
__device__ __align__(16) __nv_bfloat16 g_WimgL[FUSED * IMG_D];
__device__ __align__(16) __nv_bfloat16 g_WblkH[FUSED * BLK_D];
__device__ __align__(16) __nv_bfloat16 g_WblkL[FUSED * BLK_D];
__device__ __align__(16) __nv_bfloat16 g_WvTH[FUSED * FUSED];
__device__ __align__(16) __nv_bfloat16 g_WvTL[FUSED * FUSED];
__device__ __align__(16) __nv_bfloat16 g_WeTH[FUSED * FUSED];
__device__ __align__(16) __nv_bfloat16 g_WeTL[FUSED * FUSED];
__device__ __align__(16) __nv_bfloat16 g_fc1H[FUSED * FUSED];
__device__ __align__(16) __nv_bfloat16 g_fc1L[FUSED * FUSED];
__device__ __align__(16) __nv_bfloat16 g_fc2H[OUT_D * FUSED];
__device__ __align__(16) __nv_bfloat16 g_fc2L[OUT_D * FUSED];

// packed swizzled tile-major [kc][nt]{hi 16KB, lo 16KB} (tcgen05 path)
__device__ __align__(1024) __nv_bfloat16 g_pWimg[2 * FUSED * IMG_D];
__device__ __align__(1024) __nv_bfloat16 g_pWblk[2 * FUSED * BLK_D];
__device__ __align__(1024) __nv_bfloat16 g_pWvT[2 * FUSED * FUSED];
__device__ __align__(1024) __nv_bfloat16 g_pWeT[2 * FUSED * FUSED];
__device__ __align__(1024) __nv_bfloat16 g_pfc1[2 * FUSED * FUSED];
__device__ __align__(1024) __nv_bfloat16 g_pfc2[2 * OUT_D * FUSED];

__device__ int g_cnt0[NDST0];
__device__ int g_off0[NDST0 + 1];
__device__ int g_cur0[NDST0];
__device__ int g_csr0[E0];    // SRC node id per CSR slot
__device__ int g_cnt1[NDST1];
__device__ int g_off1[NDST1 + 1];
__device__ int g_cur1[NDST1];
__device__ int g_csr1[E1];

// ==================== common helpers ====================
__device__ __forceinline__ uint32_t smem_u32(const void* p) {
    uint32_t a;
    asm("{ .reg .u64 t; cvta.to.shared.u64 t, %1; cvt.u32.u64 %0, t; }" : "=r"(a) : "l"(p));
    return a;
}
__device__ __forceinline__ float sigm(float x) { return 1.f / (1.f + __expf(-x)); }

// ==================== tcgen05 macros ====================
#define TCGEN05_ALLOC(saddr, ncols) \
    asm volatile("tcgen05.alloc.cta_group::1.sync.aligned.shared::cta.b32 [%0], %1;" \
                 :: "r"((uint32_t)(saddr)), "r"((uint32_t)(ncols)) : "memory")
#define TCGEN05_RELINQ() \
    asm volatile("tcgen05.relinquish_alloc_permit.cta_group::1.sync.aligned;")
#define TCGEN05_DEALLOC(tm, ncols) \
    asm volatile("tcgen05.dealloc.cta_group::1.sync.aligned.b32 %0, %1;" :: "r"(tm), "r"((uint32_t)(ncols)))
#define TCGEN05_COMMIT(mbar) \
    asm volatile("tcgen05.commit.cta_group::1.mbarrier::arrive::one.shared::cluster.b64 [%0];" \
                 :: "r"((uint32_t)(mbar)) : "memory")
#define TCGEN05_FENCE_AFTER() asm volatile("tcgen05.fence::after_thread_sync;" ::: "memory")
#define TCGEN05_FENCE_BEFORE() asm volatile("tcgen05.fence::before_thread_sync;" ::: "memory")
#define TCGEN05_WAIT_LD() asm volatile("tcgen05.wait::ld.sync.aligned;" ::: "memory")
#define FENCE_ASYNC_SHARED() asm volatile("fence.proxy.async.shared::cta;" ::: "memory")
#define MBARRIER_INIT(mbar, cnt) \
    asm volatile("mbarrier.init.shared.b64 [%0], %1;" :: "r"((uint32_t)(mbar)), "r"((uint32_t)(cnt)) : "memory")

#define MBARRIER_WAIT_PARITY(mbar_addr, phase_parity) do { \
    uint32_t _mbar = (uint32_t)(mbar_addr); \
    uint32_t _par = (uint32_t)(phase_parity); \
    uint32_t _done; \
    asm volatile("{\n\t.reg .pred p;\n\t" \
        "mbarrier.try_wait.parity.acquire.cta.shared::cta.b64 p, [%1], %2;\n\t" \
        "selp.b32 %0, 1, 0, p;\n\t}" : "=r"(_done) : "r"(_mbar), "r"(_par) : "memory"); \
    if (!_done) { \
        asm volatile("{\n\t.reg .pred P1;\n\t" \
            "WL_%=:\n\t" \
            "mbarrier.try_wait.parity.acquire.cta.shared::cta.b64 P1, [%0], %1, 0x989680;\n\t" \
            "@P1 bra.uni WD_%=;\n\t" \
            "bra.uni WL_%=;\n\t" \
            "WD_%=:\n\t}" :: "r"(_mbar), "r"(_par) : "memory"); \
    } \
} while (0)

#define TCGEN05_LD_32X32B_X32(r, tmem_addr) \
    asm volatile( \
        "tcgen05.ld.sync.aligned.32x32b.x32.b32 " \
        "{%0, %1, %2, %3, %4, %5, %6, %7, " \
        " %8, %9, %10, %11, %12, %13, %14, %15, " \
        " %16, %17, %18, %19, %20, %21, %22, %23, " \
        " %24, %25, %26, %27, %28, %29, %30, %31}, [%32];" \
        : "=r"((r)[0]),  "=r"((r)[1]),  "=r"((r)[2]),  "=r"((r)[3]), \
          "=r"((r)[4]),  "=r"((r)[5]),  "=r"((r)[6]),  "=r"((r)[7]), \
          "=r"((r)[8]),  "=r"((r)[9]),  "=r"((r)[10]), "=r"((r)[11]), \
          "=r"((r)[12]), "=r"((r)[13]), "=r"((r)[14]), "=r"((r)[15]), \
          "=r"((r)[16]), "=r"((r)[17]), "=r"((r)[18]), "=r"((r)[19]), \
          "=r"((r)[20]), "=r"((r)[21]), "=r"((r)[22]), "=r"((r)[23]), \
          "=r"((r)[24]), "=r"((r)[25]), "=r"((r)[26]), "=r"((r)[27]), \
          "=r"((r)[28]), "=r"((r)[29]), "=r"((r)[30]), "=r"((r)[31]) \
        : "r"(tmem_addr))

static __device__ __forceinline__ uint64_t make_desc(uint32_t saddr) {
    const uint64_t base = (uint64_t(2) << 61) | (uint64_t(1) << 46) |
                          (uint64_t(64) << 32) | (uint64_t(1) << 16);
    return base | ((uint64_t)(saddr >> 4) & 0x3FFF);
}
#define GT_IDESC 0x8200490u

__device__ __forceinline__ void mma_f16_ss(uint32_t d, uint64_t a, uint64_t b,
                                           uint32_t idesc, uint32_t en) {
#if defined(__CUDA_ARCH__) && defined(__CUDA_ARCH_FEAT_SM103_ALL)
    asm volatile(
        "{\n\t.reg .pred p;\n\tsetp.ne.u32 p, %4, 0;\n\t"
        "tcgen05.mma.cta_group::1.kind::f16 [%0], %1, %2, %3, {%5,%5,%5,%5}, p;\n\t}"
        :: "r"(d), "l"(a), "l"(b), "r"(idesc), "r"(en), "r"(0u)
        : "memory");
#else
    (void)d; (void)a; (void)b; (void)idesc; (void)en;
#endif
}

// ==================== mma.sync fallback macros ====================
#define LDSM_X4(r0, r1, r2, r3, addr) \
    asm volatile("ldmatrix.sync.aligned.m8n8.x4.shared.b16 {%0,%1,%2,%3}, [%4];" \
                 : "=r"(r0), "=r"(r1), "=r"(r2), "=r"(r3) : "r"(addr))
#define MMA_BF16(c, a, b) \
    asm volatile("mma.sync.aligned.m16n8k16.row.col.f32.bf16.bf16.f32 " \
                 "{%0,%1,%2,%3},{%4,%5,%6,%7},{%8,%9},{%0,%1,%2,%3};" \
                 : "+f"((c)[0]), "+f"((c)[1]), "+f"((c)[2]), "+f"((c)[3]) \
                 : "r"((a)[0]), "r"((a)[1]), "r"((a)[2]), "r"((a)[3]), \
                   "r"((b)[0]), "r"((b)[1]))

// ==================== GEMM (NT) with fused epilogues ====================
// MODE 0: C = A*B^T
// MODE 1: GEMM -> ge; epilogue: C(=fused) = sig(ge+be)*ti + sig(gv+bv)*fi   (NT=4)
// MODE 2: C = z1; s0out/s1out = per-(row,head) dots with P0=a1 [8][128]     (NT=4)
// MODE 3: C = z2; s0out/s1out = per-row dots with P0=a2 [256]               (NT=1)
#define GT_THREADS 512
#define SM_A_OFF 1024
#define SM_B_OFF (1024 + 65536)
#define SM_TOTAL (1024 + 65536 + 131072)
// barriers: afree[2]@16,24  bmma[2]@32,40  done@56  bfull[2]@64,72
// B stage (65536 B): Bh(n0)@0 Bl(n0)@16384 Bh(n1)@32768 Bl(n1)@49152

// B tile synchronous (fallback path)
__device__ __forceinline__ void load_tile_bf16(const __nv_bfloat16* __restrict__ src,
                                               int ldk, int row0, int k0,
                                               char* dst, int tid) {
#pragma unroll
    for (int c = 0; c < 2; c++) {
        int chunk = tid + c * GT_THREADS;
        int r = chunk >> 3, c16 = chunk & 7;
        uint32_t off = (uint32_t)(r * 128 + c16 * 16);
        uint32_t sw = off ^ ((off >> 3) & 0x70);
        float4 v = *(const float4*)(src + (size_t)(row0 + r) * ldk + k0 + c16 * 8);
        *(float4*)(dst + sw) = v;
    }
}

// A 128x64 fp32 -> hi/lo bf16 SW128 tiles; zero rows >= rowMax
__device__ __forceinline__ void load_tile_cvt(const float* __restrict__ src,
                                              int ldk, int row0, int rowMax, int k0,
                                              char* hidst, char* lodst, int tid) {
#pragma unroll
    for (int c = 0; c < 2; c++) {
        int chunk = tid + c * GT_THREADS;
        int r = chunk >> 3, c16 = chunk & 7;
        uint32_t off = (uint32_t)(r * 128 + c16 * 16);
        uint32_t sw = off ^ ((off >> 3) & 0x70);
        int gr = row0 + r;
        float4 v0 = make_float4(0.f, 0.f, 0.f, 0.f);
        float4 v1 = make_float4(0.f, 0.f, 0.f, 0.f);
        if (gr < rowMax) {
            const float* p = src + (size_t)gr * ldk + k0 + c16 * 8;
            v0 = *(const float4*)p;
            v1 = *(const float4*)(p + 4);
        }
        float f[8] = {v0.x, v0.y, v0.z, v0.w, v1.x, v1.y, v1.z, v1.w};
        __nv_bfloat162 h[4], l[4];
#pragma unroll
        for (int j = 0; j < 4; j++) {
            __nv_bfloat16 h0 = __float2bfloat16(f[2 * j]);
            __nv_bfloat16 h1 = __float2bfloat16(f[2 * j + 1]);
            h[j].x = h0; h[j].y = h1;
            l[j].x = __float2bfloat16(f[2 * j] - __bfloat162float(h0));
            l[j].y = __float2bfloat16(f[2 * j + 1] - __bfloat162float(h1));
        }
        *(float4*)(hidst + sw) = *(float4*)h;
        *(float4*)(lodst + sw) = *(float4*)l;
    }
}

template <int MODE>
__global__ void __launch_bounds__(GT_THREADS, 1)
gemm_tc_x(const float* __restrict__ A,
          const __nv_bfloat16* __restrict__ Bh, const __nv_bfloat16* __restrict__ Bl,
          const __nv_bfloat16* __restrict__ Bp,
          float* __restrict__ C, int M, int N, int K,
          const float* __restrict__ P0, const float* __restrict__ P1,
          const float* __restrict__ P2, const float* __restrict__ P3,
          const float* __restrict__ P4,
          float* __restrict__ s0out, float* __restrict__ s1out) {
    extern __shared__ __align__(1024) char smem[];
    const int tid = threadIdx.x;
    const int wid = tid >> 5, lane = tid & 31;
    const int row0 = blockIdx.x * 128;
    const int NT = N >> 7;
    const int KCN = K >> 6;

#if defined(__CUDA_ARCH__) && !defined(__CUDA_ARCH_FEAT_SM103_ALL)
    // ================= fallback: mma.sync bf16 (warps 0-7 compute, all load) =================
    (void)Bp;
    const int wm = wid & 3;
    const int wn = (wid >> 2) & 1;
    char* sAh = smem + SM_A_OFF;
    char* sAl = smem + SM_A_OFF + 16384;
    char* sBh = smem + SM_B_OFF;
    char* sBl = smem + SM_B_OFF + 16384;
    const uint32_t uAh = smem_u32(sAh), uAl = smem_u32(sAl);
    const uint32_t uBh = smem_u32(sBh), uBl = smem_u32(sBl);
    const int g = lane >> 3, r8 = lane & 7;
    float* redf = (float*)(smem);

    for (int n = 0; n < NT; n++) {
        float acc[2][8][4];
#pragma unroll
        for (int mt = 0; mt < 2; mt++)
#pragma unroll
            for (int nt = 0; nt < 8; nt++)
#pragma unroll
                for (int e = 0; e < 4; e++) acc[mt][nt][e] = 0.f;

        for (int k = 0; k < KCN; k++) {
            __syncthreads();
            load_tile_cvt(A, K, row0, M, k * 64, sAh, sAl, tid);
            load_tile_bf16(Bh, K, n * 128, k * 64, sBh, tid);
            load_tile_bf16(Bl, K, n * 128, k * 64, sBl, tid);
            __syncthreads();
            if (wid < 8) {
#pragma unroll
                for (int kk = 0; kk < 4; kk++) {
                    const int kb = kk * 32 + (g >> 1) * 16;
                    uint32_t ah[2][4], al[2][4], bh[8][2], bl[8][2];
#pragma unroll
                    for (int mt = 0; mt < 2; mt++) {
                        uint32_t off = (uint32_t)((wm * 32 + mt * 16 + (g & 1) * 8 + r8) * 128 + kb);
                        uint32_t sw = off ^ ((off >> 3) & 0x70);
                        LDSM_X4(ah[mt][0], ah[mt][1], ah[mt][2], ah[mt][3], uAh + sw);
                        LDSM_X4(al[mt][0], al[mt][1], al[mt][2], al[mt][3], uAl + sw);
                    }
#pragma unroll
                    for (int bt = 0; bt < 4; bt++) {
                        uint32_t off = (uint32_t)((wn * 64 + bt * 16 + (g & 1) * 8 + r8) * 128 + kb);
                        uint32_t sw = off ^ ((off >> 3) & 0x70);
                        uint32_t r0, r1, r2, r3;
                        LDSM_X4(r0, r1, r2, r3, uBh + sw);
                        bh[bt * 2][0] = r0; bh[bt * 2][1] = r2;
                        bh[bt * 2 + 1][0] = r1; bh[bt * 2 + 1][1] = r3;
                        LDSM_X4(r0, r1, r2, r3, uBl + sw);
                        bl[bt * 2][0] = r0; bl[bt * 2][1] = r2;
                        bl[bt * 2 + 1][0] = r1; bl[bt * 2 + 1][1] = r3;
                    }
#pragma unroll
                    for (int mt = 0; mt < 2; mt++)
#pragma unroll
                        for (int nt = 0; nt < 8; nt++) {
                            MMA_BF16(acc[mt][nt], ah[mt], bh[nt]);
                            MMA_BF16(acc[mt][nt], ah[mt], bl[nt]);
                            MMA_BF16(acc[mt][nt], al[mt], bh[nt]);
                        }
                }
            }
        }
        __syncthreads();
        if (wid < 8) {
            const int hn = n * 2 + wn;
#pragma unroll
            for (int mt = 0; mt < 2; mt++) {
                int rr = row0 + wm * 32 + mt * 16 + (lane >> 2);
                float p0a = 0.f, p1a = 0.f, p0b = 0.f, p1b = 0.f;
#pragma unroll
                for (int nt = 0; nt < 8; nt++) {
                    int col = n * 128 + wn * 64 + nt * 8 + (lane & 3) * 2;
                    float v0 = acc[mt][nt][0], v1 = acc[mt][nt][1];
                    float v2 = acc[mt][nt][2], v3 = acc[mt][nt][3];
                    if (MODE == 2) {
                        int c = nt * 8 + (lane & 3) * 2;
                        float aS0 = __ldg(&P0[hn * 128 + c]),      aS1 = __ldg(&P0[hn * 128 + c + 1]);
                        float aD0 = __ldg(&P0[hn * 128 + 64 + c]), aD1 = __ldg(&P0[hn * 128 + 64 + c + 1]);
                        p0a += v0 * aS0 + v1 * aS1;  p1a += v0 * aD0 + v1 * aD1;
                        p0b += v2 * aS0 + v3 * aS1;  p1b += v2 * aD0 + v3 * aD1;
                    }
                    if (MODE == 3) {
                        float aS0 = __ldg(&P0[col]),       aS1 = __ldg(&P0[col + 1]);
                        float aD0 = __ldg(&P0[128 + col]), aD1 = __ldg(&P0[128 + col + 1]);
                        p0a += v0 * aS0 + v1 * aS1;  p1a += v0 * aD0 + v1 * aD1;
                        p0b += v2 * aS0 + v3 * aS1;  p1b += v2 * aD0 + v3 * aD1;
                    }
                    if (MODE == 1) {
                        float bv0 = __ldg(&P3[col]), bv1 = __ldg(&P3[col + 1]);
                        float be0 = __ldg(&P4[col]), be1 = __ldg(&P4[col + 1]);
                        if (rr < M) {
                            size_t o = (size_t)rr * N + col;
                            v0 = sigm(v0 + be0) * __ldg(&P2[o]) + sigm(__ldg(&P0[o]) + bv0) * __ldg(&P1[o]);
                            v1 = sigm(v1 + be1) * __ldg(&P2[o+1]) + sigm(__ldg(&P0[o+1]) + bv1) * __ldg(&P1[o+1]);
                        }
                        if (rr + 8 < M) {
                            size_t o = (size_t)(rr + 8) * N + col;
                            v2 = sigm(v2 + be0) * __ldg(&P2[o]) + sigm(__ldg(&P0[o]) + bv0) * __ldg(&P1[o]);
                            v3 = sigm(v3 + be1) * __ldg(&P2[o+1]) + sigm(__ldg(&P0[o+1]) + bv1) * __ldg(&P1[o+1]);
                        }
                    }
                    if (rr < M)     *(float2*)&C[(size_t)rr * N + col] = make_float2(v0, v1);
                    if (rr + 8 < M) *(float2*)&C[(size_t)(rr + 8) * N + col] = make_float2(v2, v3);
                }
                if (MODE == 2 || MODE == 3) {
                    p0a += __shfl_xor_sync(0xffffffffu, p0a, 1); p0a += __shfl_xor_sync(0xffffffffu, p0a, 2);
                    p1a += __shfl_xor_sync(0xffffffffu, p1a, 1); p1a += __shfl_xor_sync(0xffffffffu, p1a, 2);
                    p0b += __shfl_xor_sync(0xffffffffu, p0b, 1); p0b += __shfl_xor_sync(0xffffffffu, p0b, 2);
                    p1b += __shfl_xor_sync(0xffffffffu, p1b, 1); p1b += __shfl_xor_sync(0xffffffffu, p1b, 2);
                    if ((lane & 3) == 0) {
                        if (MODE == 2) {
                            if (rr < M)     { s0out[(size_t)rr * 8 + hn] = p0a; s1out[(size_t)rr * 8 + hn] = p1a; }
                            if (rr + 8 < M) { s0out[(size_t)(rr + 8) * 8 + hn] = p0b; s1out[(size_t)(rr + 8) * 8 + hn] = p1b; }
                        } else {
                            int lr = wm * 32 + mt * 16 + (lane >> 2);
                            redf[(wn * 128 + lr) * 2 + 0] = p0a;
                            redf[(wn * 128 + lr) * 2 + 1] = p1a;
                            redf[(wn * 128 + lr + 8) * 2 + 0] = p0b;
                            redf[(wn * 128 + lr + 8) * 2 + 1] = p1b;
                        }
                    }
                }
            }
        }
    }
    if (MODE == 3) {
        __syncthreads();
        if (tid < 128 && row0 + tid < M) {
            s0out[row0 + tid] = redf[tid * 2] + redf[(128 + tid) * 2];
            s1out[row0 + tid] = redf[tid * 2 + 1] + redf[(128 + tid) * 2 + 1];
        }
    }
#else
    // ================= tcgen05: n-pair iters, B via cp.async.bulk of packed tiles =================
    uint32_t sbase = smem_u32(smem);
    if (wid == 0) { TCGEN05_ALLOC(sbase, 512); TCGEN05_RELINQ(); }
    if (tid == 0) {
        MBARRIER_INIT(sbase + 16, 1);
        MBARRIER_INIT(sbase + 24, 1);
        MBARRIER_INIT(sbase + 32, 1);
        MBARRIER_INIT(sbase + 40, 1);
        MBARRIER_INIT(sbase + 56, 1);
        MBARRIER_INIT(sbase + 64, 1);
        MBARRIER_INIT(sbase + 72, 1);
    }
    __syncthreads();
    uint32_t tmem;
    asm volatile("ld.shared.b32 %0, [%1];" : "=r"(tmem) : "r"(sbase));

    const int NTH = (NT + 1) >> 1;
    const int ITER = KCN * NTH;
    uint32_t pa = 0, pmma = 0, pfull = 0;

#define BULK_PAIR(kk_, n0_, slot_) do {                                                \
        uint32_t _bytes = (((n0_) + 1 < NT) ? 65536u : 32768u);                        \
        uint32_t _mb = sbase + 64 + (slot_) * 8;                                       \
        asm volatile("mbarrier.arrive.expect_tx.shared.b64 _, [%0], %1;"               \
                     :: "r"(_mb), "r"(_bytes) : "memory");                             \
        const char* _src = (const char*)Bp + ((size_t)((kk_) * NT + (n0_))) * 32768;   \
        asm volatile("cp.async.bulk.shared::cta.global.mbarrier::complete_tx::bytes "  \
                     "[%0], [%1], %2, [%3];"                                           \
                     :: "r"(sbase + SM_B_OFF + (slot_) * 65536), "l"(_src),            \
                        "r"(_bytes), "r"(_mb) : "memory");                             \
    } while (0)

    // prologue: B stages for iter 0,1 in flight; A chunk 0 resident
    if (tid == 0) {
        BULK_PAIR(0, 0, 0);
        if (ITER > 1) {
            int k1 = 1 / NTH, p1 = 1 % NTH;
            BULK_PAIR(k1, 2 * p1, 1);
        }
    }
    load_tile_cvt(A, K, row0, M, 0, smem + SM_A_OFF, smem + SM_A_OFF + 16384, tid);

    for (int iter = 0; iter < ITER; iter++) {
        const int k = iter / NTH, p = iter - k * NTH;
        const int n0 = 2 * p;
        const int sa = k & 1;
        const int sb = iter & 1;

        // B pair for this iter arrived
        MBARRIER_WAIT_PARITY(sbase + 64 + sb * 8, (pfull >> sb) & 1u);
        pfull ^= (1u << sb);
        FENCE_ASYNC_SHARED();
        __syncthreads();

        if (tid == 0) {
            uint64_t adh = make_desc(sbase + SM_A_OFF + sa * 32768);
            uint64_t adl = make_desc(sbase + SM_A_OFF + sa * 32768 + 16384);
            uint32_t stb = sbase + SM_B_OFF + sb * 65536;
#pragma unroll
            for (int nn = 0; nn < 2; nn++) {
                if (n0 + nn >= NT) break;
                uint64_t bdh = make_desc(stb + nn * 32768);
                uint64_t bdl = make_desc(stb + nn * 32768 + 16384);
                uint32_t d = tmem + (n0 + nn) * 128;
#pragma unroll
                for (int t = 0; t < 4; t++)
                    mma_f16_ss(d, adh + t * 2, bdh + t * 2, GT_IDESC,
                               (k > 0 || t > 0) ? 1u : 0u);
#pragma unroll
                for (int t = 0; t < 4; t++)
                    mma_f16_ss(d, adh + t * 2, bdl + t * 2, GT_IDESC, 1u);
#pragma unroll
                for (int t = 0; t < 4; t++)
                    mma_f16_ss(d, adl + t * 2, bdh + t * 2, GT_IDESC, 1u);
            }
            TCGEN05_COMMIT(sbase + 32 + sb * 8);
            if (p == NTH - 1) TCGEN05_COMMIT(sbase + 16 + sa * 8);
            if (iter == ITER - 1) TCGEN05_COMMIT(sbase + 56);

            // refill this slot for iter+2 once its MMAs complete
            if (iter + 2 < ITER) {
                MBARRIER_WAIT_PARITY(sbase + 32 + sb * 8, (pmma >> sb) & 1u);
                pmma ^= (1u << sb);
                const int i2 = iter + 2;
                const int k2 = i2 / NTH, p2 = i2 - k2 * NTH;
                BULK_PAIR(k2, 2 * p2, sb);
            }
        }

        // prefetch A chunk k+1 during first pair of chunk k
        if (p == 0 && k + 1 < KCN) {
            const int sa2 = (k + 1) & 1;
            if (k >= 1) {
                MBARRIER_WAIT_PARITY(sbase + 16 + sa2 * 8, (pa >> sa2) & 1u);
                pa ^= (1u << sa2);
            }
            load_tile_cvt(A, K, row0, M, (k + 1) * 64,
                          smem + SM_A_OFF + sa2 * 32768,
                          smem + SM_A_OFF + sa2 * 32768 + 16384, tid);
        }
    }
#undef BULK_PAIR

    __syncthreads();
    MBARRIER_WAIT_PARITY(sbase + 56, 0);
    TCGEN05_FENCE_AFTER();

    // epilogue: 16 warps, 4 groups over column blocks (stride 4)
    const int eg = wid >> 2;
    const int lrow = (wid & 3) * 32 + lane;
    const int row = row0 + lrow;
    float* red = (float*)(smem + SM_A_OFF);  // tiles dead

    for (int cb = eg; cb < NT * 4; cb += 4) {
        uint32_t r[32];
        TCGEN05_LD_32X32B_X32(r, tmem + cb * 32);
        TCGEN05_WAIT_LD();
        float v[32];
#pragma unroll
        for (int c = 0; c < 32; c++) v[c] = __uint_as_float(r[c]);

        if (MODE == 1) {
            if (row < M) {
                const float4* gv4 = (const float4*)(P0 + (size_t)row * N + cb * 32);
                const float4* fi4 = (const float4*)(P1 + (size_t)row * N + cb * 32);
                const float4* ti4 = (const float4*)(P2 + (size_t)row * N + cb * 32);
                const float4* bv4 = (const float4*)(P3 + cb * 32);
                const float4* be4 = (const float4*)(P4 + cb * 32);
                float4* cp = (float4*)(C + (size_t)row * N + cb * 32);
#pragma unroll
                for (int j = 0; j < 8; j++) {
                    float4 gg = __ldg(&gv4[j]), ff = __ldg(&fi4[j]), tt = __ldg(&ti4[j]);
                    float4 bb = __ldg(&bv4[j]), ee = __ldg(&be4[j]);
                    float4 o;
                    o.x = sigm(v[4*j+0] + ee.x) * tt.x + sigm(gg.x + bb.x) * ff.x;
                    o.y = sigm(v[4*j+1] + ee.y) * tt.y + sigm(gg.y + bb.y) * ff.y;
                    o.z = sigm(v[4*j+2] + ee.z) * tt.z + sigm(gg.z + bb.z) * ff.z;
                    o.w = sigm(v[4*j+3] + ee.w) * tt.w + sigm(gg.w + bb.w) * ff.w;
                    cp[j] = o;
                }
            }
        } else {
            if (row < M) {
                float* cp = C + (size_t)row * N + cb * 32;
#pragma unroll
                for (int c = 0; c < 32; c += 4)
                    *(float4*)(cp + c) = make_float4(v[c], v[c+1], v[c+2], v[c+3]);
            }
            if (MODE == 2) {
                int head = cb >> 1;
                int within = (cb & 1) * 32;
                float s0 = 0.f, s1 = 0.f;
#pragma unroll
                for (int c = 0; c < 32; c++) {
                    s0 += v[c] * __ldg(&P0[head * 128 + within + c]);
                    s1 += v[c] * __ldg(&P0[head * 128 + 64 + within + c]);
                }
                red[(cb * 128 + lrow) * 2 + 0] = s0;
                red[(cb * 128 + lrow) * 2 + 1] = s1;
            }
            if (MODE == 3) {
                float s0 = 0.f, s1 = 0.f;
#pragma unroll
                for (int c = 0; c < 32; c++) {
                    int col = cb * 32 + c;
                    s0 += v[c] * __ldg(&P0[col]);
                    s1 += v[c] * __ldg(&P0[128 + col]);
                }
                red[(cb * 128 + lrow) * 2 + 0] = s0;
                red[(cb * 128 + lrow) * 2 + 1] = s1;
            }
        }
    }
    TCGEN05_FENCE_BEFORE();
    __syncthreads();
    if (MODE == 2) {
        for (int idx = tid; idx < 1024; idx += GT_THREADS) {
            int lr = idx >> 3, h = idx & 7;
            if (row0 + lr < M) {
                s0out[(size_t)(row0 + lr) * 8 + h] =
                    red[((2*h) * 128 + lr) * 2] + red[((2*h+1) * 128 + lr) * 2];
                s1out[(size_t)(row0 + lr) * 8 + h] =
                    red[((2*h) * 128 + lr) * 2 + 1] + red[((2*h+1) * 128 + lr) * 2 + 1];
            }
        }
    }
    if (MODE == 3) {
        if (tid < 128 && row0 + tid < M) {
            float s0 = 0.f, s1 = 0.f;
#pragma unroll
            for (int cb = 0; cb < 4; cb++) {
                s0 += red[(cb * 128 + tid) * 2];
                s1 += red[(cb * 128 + tid) * 2 + 1];
            }
            s0out[row0 + tid] = s0;
            s1out[row0 + tid] = s1;
        }
    }
    __syncthreads();
    if (wid == 0) TCGEN05_DEALLOC(tmem, 512);
#endif
}

// ---------------- weight prep ----------------
// flat hi/lo (fallback)
__global__ void cvt_hilo(const float* __restrict__ in, __nv_bfloat16* __restrict__ hi,
                         __nv_bfloat16* __restrict__ lo, int n4) {
    int i = blockIdx.x * blockDim.x + threadIdx.x;
    if (i >= n4) return;
    float4 v = ((const float4*)in)[i];
    float f[4] = {v.x, v.y, v.z, v.w};
    __nv_bfloat162 h01, h23, l01, l23;
    __nv_bfloat16 h0 = __float2bfloat16(f[0]), h1 = __float2bfloat16(f[1]);
    __nv_bfloat16 h2 = __float2bfloat16(f[2]), h3 = __float2bfloat16(f[3]);
    h01.x = h0; h01.y = h1; h23.x = h2; h23.y = h3;
    l01.x = __float2bfloat16(f[0] - __bfloat162float(h0));
    l01.y = __float2bfloat16(f[1] - __bfloat162float(h1));
    l23.x = __float2bfloat16(f[2] - __bfloat162float(h2));
    l23.y = __float2bfloat16(f[3] - __bfloat162float(h3));
    ((__nv_bfloat162*)hi)[2 * i] = h01;
    ((__nv_bfloat162*)hi)[2 * i + 1] = h23;
    ((__nv_bfloat162*)lo)[2 * i] = l01;
    ((__nv_bfloat162*)lo)[2 * i + 1] = l23;
}

__global__ void cvt_hilo_T(const float* __restrict__ in, __nv_bfloat16* __restrict__ hi,
                           __nv_bfloat16* __restrict__ lo) {
    __shared__ float t[32][33];
    int x = blockIdx.x * 32 + threadIdx.x;
    int y0 = blockIdx.y * 32 + threadIdx.y;
#pragma unroll
    for (int r = 0; r < 32; r += 8)
        t[threadIdx.y + r][threadIdx.x] = in[(size_t)(y0 + r) * 512 + x];
    __syncthreads();
    int x2 = blockIdx.y * 32 + threadIdx.x;
    int y2 = blockIdx.x * 32 + threadIdx.y;
#pragma unroll
    for (int r = 0; r < 32; r += 8) {
        float f = t[threadIdx.x][threadIdx.y + r];
        __nv_bfloat16 h = __float2bfloat16(f);
        hi[(size_t)(y2 + r) * 512 + x2] = h;
        lo[(size_t)(y2 + r) * 512 + x2] = __float2bfloat16(f - __bfloat162float(h));
    }
}

// packed swizzled tile-major: out[kc][nt]{hi 16KB, lo 16KB}; TRANS: B[n][k] = W[k][n]
template <int TRANS>
__global__ void pack_w(const float* __restrict__ W, __nv_bfloat16* __restrict__ outp,
                       int N, int K) {
    const int NT = N >> 7;
    const int nt = blockIdx.x, kc = blockIdx.y;
    char* base = (char*)outp + ((size_t)(kc * NT + nt)) * 32768;
#pragma unroll
    for (int c = 0; c < 4; c++) {
        int chunk = threadIdx.x + c * 256;
        int r = chunk >> 3, c16 = chunk & 7;
        uint32_t off = (uint32_t)(r * 128 + c16 * 16);
        uint32_t sw = off ^ ((off >> 3) & 0x70);
        int n = nt * 128 + r;
        int k0 = kc * 64 + c16 * 8;
        float f[8];
#pragma unroll
        for (int j = 0; j < 8; j++)
            f[j] = TRANS ? __ldg(&W[(size_t)(k0 + j) * N + n])
                         : __ldg(&W[(size_t)n * K + k0 + j]);
        __nv_bfloat162 h[4], l[4];
#pragma unroll
        for (int j = 0; j < 4; j++) {
            __nv_bfloat16 h0 = __float2bfloat16(f[2 * j]);
            __nv_bfloat16 h1 = __float2bfloat16(f[2 * j + 1]);
            h[j].x = h0; h[j].y = h1;
            l[j].x = __float2bfloat16(f[2 * j] - __bfloat162float(h0));
            l[j].y = __float2bfloat16(f[2 * j + 1] - __bfloat162float(h1));
        }
        *(float4*)(base + sw) = *(float4*)h;
        *(float4*)(base + 16384 + sw) = *(float4*)l;
    }
}

// ---------------- CSR build (csr stores SRC id) ----------------
__global__ void zero_int(int* p, int n) {
    int i = blockIdx.x * blockDim.x + threadIdx.x;
    if (i < n) p[i] = 0;
}
__global__ void edge_count(const int* __restrict__ dst, int* __restrict__ cnt, int E) {
    int i = blockIdx.x * blockDim.x + threadIdx.x;
    if (i < E) atomicAdd(&cnt[dst[i]], 1);
}
__global__ void scan_kernel(const int* __restrict__ cnt, int* __restrict__ off,
                            int* __restrict__ cursor, int n) {
    __shared__ int sh[1024];
    __shared__ int carry_s;
    int tid = threadIdx.x;
    if (tid == 0) carry_s = 0;
    __syncthreads();
    for (int base = 0; base < n; base += 1024) {
        int v = (base + tid < n) ? cnt[base + tid] : 0;
        sh[tid] = v;
        __syncthreads();
        for (int d = 1; d < 1024; d <<= 1) {
            int t = (tid >= d) ? sh[tid - d] : 0;
            __syncthreads();
            sh[tid] += t;
            __syncthreads();
        }
        int carry = carry_s;
        if (base + tid < n) {
            int ex = carry + sh[tid] - v;
            off[base + tid] = ex;
            cursor[base + tid] = ex;
        }
        __syncthreads();
        if (tid == 1023) carry_s = carry + sh[1023];
        __syncthreads();
    }
    if (tid == 0) off[n] = carry_s;
}
__global__ void edge_scatter(const int* __restrict__ src, const int* __restrict__ dst,
                             int* __restrict__ cursor, int* __restrict__ csr, int E) {
    int i = blockIdx.x * blockDim.x + threadIdx.x;
    if (i < E) {
        int p = atomicAdd(&cursor[dst[i]], 1);
        csr[p] = src[i];
    }
}

// ---------------- GAT layer 1: warp-per-dst softmax + aggregate + ELU ----------------
__global__ void gat_agg1(const int* __restrict__ off, const int* __restrict__ csr,
                         const float* __restrict__ ssrc, const float* __restrict__ sdst,
                         const float* __restrict__ z, float* __restrict__ hout, int nd) {
    int w = (blockIdx.x * blockDim.x + threadIdx.x) >> 5;
    int lane = threadIdx.x & 31;
    if (w >= nd) return;
    int h = lane & 7;
    int o0 = off[w], o1 = off[w + 1];
    float sd = sdst[(size_t)w * 8 + h];

    float mx = -1e30f;
    for (int i = o0; i < o1; i++) {
        int s = __ldg(&csr[i]);
        float v = __ldg(&ssrc[(size_t)s * 8 + h]) + sd;
        v = (v >= 0.f) ? v : 0.01f * v;
        mx = fmaxf(mx, v);
    }
    float den = 0.f;
    for (int i = o0; i < o1; i++) {
        int s = __ldg(&csr[i]);
        float v = __ldg(&ssrc[(size_t)s * 8 + h]) + sd;
        v = (v >= 0.f) ? v : 0.01f * v;
        den += __expf(v - mx);
    }
    float inv = 1.f / den;

    float acc[16];
#pragma unroll
    for (int j = 0; j < 16; j++) acc[j] = 0.f;

    for (int i = o0; i < o1; i++) {
        int s = __ldg(&csr[i]);
        float v = __ldg(&ssrc[(size_t)s * 8 + h]) + sd;
        v = (v >= 0.f) ? v : 0.01f * v;
        float al = __expf(v - mx) * inv;
        const float* zp = z + (size_t)s * FUSED;
#pragma unroll
        for (int j = 0; j < 16; j++) {
            float a = __shfl_sync(0xffffffffu, al, j >> 1);
            acc[j] += a * __ldg(&zp[j * 32 + lane]);
        }
    }
    float* hp = hout + (size_t)w * FUSED;
#pragma unroll
    for (int j = 0; j < 16; j++) {
        float x = acc[j];
        hp[j * 32 + lane] = (x > 0.f) ? x : (__expf(x) - 1.f);
    }
}

// ---------------- GAT layer 2 (1 head, O=128) -> d_out ----------------
__global__ void gat_agg2(const int* __restrict__ off, const int* __restrict__ csr,
                         const float* __restrict__ ssrc, const float* __restrict__ sdst,
                         const float* __restrict__ z, float* __restrict__ out, int nd) {
    int w = (blockIdx.x * blockDim.x + threadIdx.x) >> 5;
    int lane = threadIdx.x & 31;
    if (w >= nd) return;
    int o0 = off[w], o1 = off[w + 1];
    float sd = sdst[w];

    float mx = -1e30f;
    for (int i = o0; i < o1; i++) {
        int s = __ldg(&csr[i]);
        float v = __ldg(&ssrc[s]) + sd;
        v = (v >= 0.f) ? v : 0.01f * v;
        mx = fmaxf(mx, v);
    }
    float den = 0.f;
    for (int i = o0; i < o1; i++) {
        int s = __ldg(&csr[i]);
        float v = __ldg(&ssrc[s]) + sd;
        v = (v >= 0.f) ? v : 0.01f * v;
        den += __expf(v - mx);
    }
    float inv = 1.f / den;

    float a0 = 0.f, a1 = 0.f, a2 = 0.f, a3 = 0.f;
    for (int i = o0; i < o1; i++) {
        int s = __ldg(&csr[i]);
        float v = __ldg(&ssrc[s]) + sd;
        v = (v >= 0.f) ? v : 0.01f * v;
        float al = __expf(v - mx) * inv;
        const float* zp = z + (size_t)s * OUT_D;
        a0 += al * __ldg(&zp[lane]);
        a1 += al * __ldg(&zp[32 + lane]);
        a2 += al * __ldg(&zp[64 + lane]);
        a3 += al * __ldg(&zp[96 + lane]);
    }
    float* op = out + (size_t)w * OUT_D;
    op[lane] = a0;
    op[32 + lane] = a1;
    op[64 + lane] = a2;
    op[96 + lane] = a3;
}

// ---------------- host ----------------
extern "C" void kernel_launch(void* const* d_in, const int* in_sizes, int n_in,
                              void* d_out, int out_size) {
    const float* img   = (const float*)d_in[0];
    const float* blk   = (const float*)d_in[1];
    const float* W_img = (const float*)d_in[2];
    const float* W_blk = (const float*)d_in[3];
    const float* Wv    = (const float*)d_in[4];
    const float* bv    = (const float*)d_in[5];
    const float* We    = (const float*)d_in[6];
    const float* be    = (const float*)d_in[7];
    const float* fc1   = (const float*)d_in[8];
    const float* a1    = (const float*)d_in[9];
    const float* fc2   = (const float*)d_in[10];
    const float* a2    = (const float*)d_in[11];
    const int*   e0s   = (const int*)d_in[12];
    const int*   e0d   = (const int*)d_in[13];
    const int*   e1s   = (const int*)d_in[14];
    const int*   e1d   = (const int*)d_in[15];
    float* out = (float*)d_out;

    float *fi, *ti, *gv, *fused, *z1, *s1s, *s1d, *hbuf, *z2, *s2s, *s2d;
    __nv_bfloat16 *WimgH, *WimgL, *WblkH, *WblkL, *WvTH, *WvTL, *WeTH, *WeTL;
    __nv_bfloat16 *fc1H, *fc1L, *fc2H, *fc2L;
    __nv_bfloat16 *pWimg, *pWblk, *pWvT, *pWeT, *pfc1, *pfc2;
    int *cnt0, *off0, *cur0, *csr0, *cnt1, *off1, *cur1, *csr1;
    cudaGetSymbolAddress((void**)&fi, g_fi);
    cudaGetSymbolAddress((void**)&ti, g_ti);
    cudaGetSymbolAddress((void**)&gv, g_gv);
    cudaGetSymbolAddress((void**)&fused, g_fused);
    cudaGetSymbolAddress((void**)&z1, g_z1);
    cudaGetSymbolAddress((void**)&s1s, g_s1s);
    cudaGetSymbolAddress((void**)&s1d, g_s1d);
    cudaGetSymbolAddress((void**)&hbuf, g_h);
    cudaGetSymbolAddress((void**)&z2, g_z2);
    cudaGetSymbolAddress((void**)&s2s, g_s2s);
    cudaGetSymbolAddress((void**)&s2d, g_s2d);
    cudaGetSymbolAddress((void**)&WimgH, g_WimgH);
    cudaGetSymbolAddress((void**)&WimgL, g_WimgL);
    cudaGetSymbolAddress((void**)&WblkH, g_WblkH);
    cudaGetSymbolAddress((void**)&WblkL, g_WblkL);
    cudaGetSymbolAddress((void**)&WvTH, g_WvTH);
    cudaGetSymbolAddress((void**)&WvTL, g_WvTL);
    cudaGetSymbolAddress((void**)&WeTH, g_WeTH);
    cudaGetSymbolAddress((void**)&WeTL, g_WeTL);
    cudaGetSymbolAddress((void**)&fc1H, g_fc1H);
    cudaGetSymbolAddress((void**)&fc1L, g_fc1L);
    cudaGetSymbolAddress((void**)&fc2H, g_fc2H);
    cudaGetSymbolAddress((void**)&fc2L, g_fc2L);
    cudaGetSymbolAddress((void**)&pWimg, g_pWimg);
    cudaGetSymbolAddress((void**)&pWblk, g_pWblk);
    cudaGetSymbolAddress((void**)&pWvT, g_pWvT);
    cudaGetSymbolAddress((void**)&pWeT, g_pWeT);
    cudaGetSymbolAddress((void**)&pfc1, g_pfc1);
    cudaGetSymbolAddress((void**)&pfc2, g_pfc2);
    cudaGetSymbolAddress((void**)&cnt0, g_cnt0);
    cudaGetSymbolAddress((void**)&off0, g_off0);
    cudaGetSymbolAddress((void**)&cur0, g_cur0);
    cudaGetSymbolAddress((void**)&csr0, g_csr0);
    cudaGetSymbolAddress((void**)&cnt1, g_cnt1);
    cudaGetSymbolAddress((void**)&off1, g_off1);
    cudaGetSymbolAddress((void**)&cur1, g_cur1);
    cudaGetSymbolAddress((void**)&csr1, g_csr1);

    cudaFuncSetAttribute(gemm_tc_x<0>, cudaFuncAttributeMaxDynamicSharedMemorySize, SM_TOTAL);
    cudaFuncSetAttribute(gemm_tc_x<1>, cudaFuncAttributeMaxDynamicSharedMemorySize, SM_TOTAL);
    cudaFuncSetAttribute(gemm_tc_x<2>, cudaFuncAttributeMaxDynamicSharedMemorySize, SM_TOTAL);
    cudaFuncSetAttribute(gemm_tc_x<3>, cudaFuncAttributeMaxDynamicSharedMemorySize, SM_TOTAL);

    const dim3 tb(256);
    const dim3 tr_grid(16, 16), tr_blk(32, 8);
    const int MT0 = (NSRC0 + 127) / 128;
    const int MT1 = (NSRC1 + 127) / 128;
    const float* NP = nullptr;

    // prep for gemm1, then gemm1 early (ncu window)
    cvt_hilo<<<(FUSED * IMG_D / 4 + 255) / 256, tb>>>(W_img, WimgH, WimgL, FUSED * IMG_D / 4);
    pack_w<0><<<dim3(4, 16), tb>>>(W_img, pWimg, FUSED, IMG_D);
    pack_w<0><<<dim3(4, 12), tb>>>(W_blk, pWblk, FUSED, BLK_D);
    gemm_tc_x<0><<<MT0, GT_THREADS, SM_TOTAL>>>(img, WimgH, WimgL, pWimg, fi, NSRC0, FUSED, IMG_D,
                                                NP, NP, NP, NP, NP, nullptr, nullptr);
    cvt_hilo<<<(FUSED * BLK_D / 4 + 255) / 256, tb>>>(W_blk, WblkH, WblkL, FUSED * BLK_D / 4);
    cvt_hilo_T<<<tr_grid, tr_blk>>>(Wv, WvTH, WvTL);
    cvt_hilo_T<<<tr_grid, tr_blk>>>(We, WeTH, WeTL);
    cvt_hilo<<<(FUSED * FUSED / 4 + 255) / 256, tb>>>(fc1, fc1H, fc1L, FUSED * FUSED / 4);
    cvt_hilo<<<(OUT_D * FUSED / 4 + 255) / 256, tb>>>(fc2, fc2H, fc2L, OUT_D * FUSED / 4);
    pack_w<1><<<dim3(4, 8), tb>>>(Wv, pWvT, FUSED, FUSED);
    pack_w<1><<<dim3(4, 8), tb>>>(We, pWeT, FUSED, FUSED);
    pack_w<0><<<dim3(4, 8), tb>>>(fc1, pfc1, FUSED, FUSED);
    pack_w<0><<<dim3(1, 8), tb>>>(fc2, pfc2, OUT_D, FUSED);
    gemm_tc_x<0><<<MT0, GT_THREADS, SM_TOTAL>>>(blk, WblkH, WblkL, pWblk, ti, NSRC0, FUSED, BLK_D,
                                                NP, NP, NP, NP, NP, nullptr, nullptr);

    // CSR builds
    zero_int<<<(NDST0 + 255) / 256, tb>>>(cnt0, NDST0);
    edge_count<<<(E0 + 255) / 256, tb>>>(e0d, cnt0, E0);
    scan_kernel<<<1, 1024>>>(cnt0, off0, cur0, NDST0);
    edge_scatter<<<(E0 + 255) / 256, tb>>>(e0s, e0d, cur0, csr0, E0);
    zero_int<<<(NDST1 + 255) / 256, tb>>>(cnt1, NDST1);
    edge_count<<<(E1 + 255) / 256, tb>>>(e1d, cnt1, E1);
    scan_kernel<<<1, 1024>>>(cnt1, off1, cur1, NDST1);
    edge_scatter<<<(E1 + 255) / 256, tb>>>(e1s, e1d, cur1, csr1, E1);

    // gv = fi x WvT ; fused = gate(ge) fused epilogue
    gemm_tc_x<0><<<MT0, GT_THREADS, SM_TOTAL>>>(fi, WvTH, WvTL, pWvT, gv, NSRC0, FUSED, FUSED,
                                                NP, NP, NP, NP, NP, nullptr, nullptr);
    gemm_tc_x<1><<<MT0, GT_THREADS, SM_TOTAL>>>(ti, WeTH, WeTL, pWeT, fused, NSRC0, FUSED, FUSED,
                                                gv, fi, ti, bv, be, nullptr, nullptr);

    // GAT layer 1
    gemm_tc_x<2><<<MT0, GT_THREADS, SM_TOTAL>>>(fused, fc1H, fc1L, pfc1, z1, NSRC0, FUSED, FUSED,
                                                a1, NP, NP, NP, NP, s1s, s1d);
    gat_agg1<<<(NDST0 * 32 + 255) / 256, tb>>>(off0, csr0, s1s, s1d, z1, hbuf, NDST0);

    // GAT layer 2
    gemm_tc_x<3><<<MT1, GT_THREADS, SM_TOTAL>>>(hbuf, fc2H, fc2L, pfc2, z2, NSRC1, OUT_D, FUSED,
                                                a2, NP, NP, NP, NP, s2s, s2d);
    gat_agg2<<<(NDST1 * 32 + 255) / 256, tb>>>(off1, csr1, s2s, s2d, z2, out, NDST1);

    (void)in_sizes; (void)n_in; (void)out_size;
}